// round 8
// baseline (speedup 1.0000x reference)
#include <cuda_runtime.h>
#include <cstdint>

#define Nn     4096
#define IND    256
#define HH     4
#define DD     64
#define HD     256
#define JSPLIT 4
#define BM     128
#define BK     32
#define NCH    ((Nn / JSPLIT) / BK)     // 32 chunks
#define SWP    36                        // sW row stride (floats) -> conflict-free frags

// ---------------- scratch (device globals; no allocation allowed) ------------
__device__ __align__(16) float g_Wh [Nn * HD];            // fp32 Wh [node][h*64+d]
__device__ __align__(16) float g_Yp [HH * 512 * DD * 8];  // tf32 [h][g][d][jj'] frag order
__device__ __align__(16) float g_Ei1[Nn * HH];            // exp(e_i)
__device__ __align__(16) float g_Ei2[Nn * HH];            // exp(0.2 e_i)
__device__ __align__(16) float g_Ej1[Nn * HH];            // exp(e_j)
__device__ __align__(16) float g_Ej2[Nn * HH];            // exp(0.2 e_j)
__device__ __align__(16) float g_part[JSPLIT][Nn * HD];
__device__ __align__(16) float g_denp[JSPLIT][Nn * HH];
__device__ int g_nop;

__device__ __forceinline__ unsigned tf32r(float x) {
    unsigned u;
    asm("cvt.rna.tf32.f32 %0, %1;" : "=r"(u) : "f"(x));
    return u;
}
__device__ __forceinline__ void mma8(float* c, const unsigned* a, unsigned b0, unsigned b1) {
    asm volatile(
        "mma.sync.aligned.m16n8k8.row.col.f32.tf32.tf32.f32 "
        "{%0,%1,%2,%3}, {%4,%5,%6,%7}, {%8,%9}, {%0,%1,%2,%3};"
        : "+f"(c[0]), "+f"(c[1]), "+f"(c[2]), "+f"(c[3])
        : "r"(a[0]), "r"(a[1]), "r"(a[2]), "r"(a[3]), "r"(b0), "r"(b1));
}

// dummy launch: keeps ncu's fixed capture slot on k3
__global__ void k0_nop() { g_nop = 0; }

// ---------------- K1: Wh = h @ W ; also emit fragment-ordered tf32 copy ------
__global__ __launch_bounds__(256) void k1_gemm(const float* __restrict__ h,
                                               const float* __restrict__ W) {
    __shared__ float As[16][64 + 4];
    __shared__ float Bs[16][64];
    __shared__ float til[64][68];
    int t  = threadIdx.x;
    int tx = t & 15, ty = t >> 4;
    int j0 = blockIdx.y * 64;
    int n0 = blockIdx.x * 64;
    float acc[4][4];
#pragma unroll
    for (int m = 0; m < 4; m++)
#pragma unroll
        for (int c = 0; c < 4; c++) acc[m][c] = 0.f;

    for (int k0 = 0; k0 < IND; k0 += 16) {
        int arow = t >> 2, akq = (t & 3) * 4;
        float4 av = *(const float4*)&h[(j0 + arow) * IND + k0 + akq];
        As[akq + 0][arow] = av.x; As[akq + 1][arow] = av.y;
        As[akq + 2][arow] = av.z; As[akq + 3][arow] = av.w;
        int brow = t >> 4, bcol = (t & 15) * 4;
        *(float4*)&Bs[brow][bcol] = *(const float4*)&W[(k0 + brow) * HD + n0 + bcol];
        __syncthreads();
#pragma unroll
        for (int kk = 0; kk < 16; kk++) {
            float a0 = As[kk][ty * 4 + 0], a1 = As[kk][ty * 4 + 1];
            float a2 = As[kk][ty * 4 + 2], a3 = As[kk][ty * 4 + 3];
            float4 b = *(float4*)&Bs[kk][tx * 4];
            acc[0][0] += a0 * b.x; acc[0][1] += a0 * b.y; acc[0][2] += a0 * b.z; acc[0][3] += a0 * b.w;
            acc[1][0] += a1 * b.x; acc[1][1] += a1 * b.y; acc[1][2] += a1 * b.z; acc[1][3] += a1 * b.w;
            acc[2][0] += a2 * b.x; acc[2][1] += a2 * b.y; acc[2][2] += a2 * b.z; acc[2][3] += a2 * b.w;
            acc[3][0] += a3 * b.x; acc[3][1] += a3 * b.y; acc[3][2] += a3 * b.z; acc[3][3] += a3 * b.w;
        }
        __syncthreads();
    }
#pragma unroll
    for (int m = 0; m < 4; m++) {
        *(float4*)&til[ty * 4 + m][tx * 4] =
            make_float4(acc[m][0], acc[m][1], acc[m][2], acc[m][3]);
#pragma unroll
        for (int c = 0; c < 4; c++)
            g_Wh[(j0 + ty * 4 + m) * HD + n0 + tx * 4 + c] = acc[m][c];
    }
    __syncthreads();

    int hh = blockIdx.x;
    float* dst = g_Yp + (hh * 512 + blockIdx.y * 8) * 512;
#pragma unroll
    for (int it = 0; it < 16; it++) {
        int idx = it * 256 + t;
        int jj  = ((idx & 1) << 2) | ((idx >> 1) & 3);   // inverse perm
        float v = til[(idx >> 9) * 8 + jj][(idx >> 3) & 63];
        dst[idx] = __uint_as_float(tf32r(v));
    }
}

// ---------------- K2: per-node attention logits + exps -----------------------
__global__ __launch_bounds__(256) void k2_e(const float* __restrict__ a) {
    int i = blockIdx.x;
    int t = threadIdx.x;
    int hh = t >> 6, d = t & 63;
    float v  = g_Wh[i * HD + t];
    float ei = v * a[hh * (2 * DD) + d];
    float ej = v * a[hh * (2 * DD) + DD + d];
#pragma unroll
    for (int o = 16; o > 0; o >>= 1) {
        ei += __shfl_down_sync(0xffffffffu, ei, o);
        ej += __shfl_down_sync(0xffffffffu, ej, o);
    }
    __shared__ float sei[8], sej[8];
    int w = t >> 5;
    if ((t & 31) == 0) { sei[w] = ei; sej[w] = ej; }
    __syncthreads();
    if (t < HH) {
        float EI = sei[2 * t] + sei[2 * t + 1];
        float EJ = sej[2 * t] + sej[2 * t + 1];
        g_Ei1[i * HH + t] = __expf(EI);
        g_Ei2[i * HH + t] = __expf(0.2f * EI);
        g_Ej1[i * HH + t] = __expf(EJ);
        g_Ej2[i * HH + t] = __expf(0.2f * EJ);
    }
}

// ---------------- K3: fused weight build + mma.sync tf32 contraction ---------
// 16 warps = 4 heads x 4 m-quarters; BM=128 rows; 128 CTAs (1 wave).
// Pipeline per chunk: issue adj LDGs (cc+1) -> MMA (cc) -> exp/STS build (cc+1).
// smem: sW 2 x [4h][128][SWP], sE1/sE2[512], sEj1/sEj2[4096]
#define SWBUF  (HH * BM * SWP)           // 18432 floats
#define OFF_E1 (2 * SWBUF)
#define OFF_E2 (OFF_E1 + 512)
#define OFF_J1 (OFF_E2 + 512)
#define OFF_J2 (OFF_J1 + 4096)
#define SMEM_K3 ((OFF_J2 + 4096) * 4)    // 184320 B

__global__ __launch_bounds__(512, 1) void k3_main(const float* __restrict__ adj) {
    extern __shared__ float sm[];
    float* sE1  = sm + OFF_E1;
    float* sE2  = sm + OFF_E2;
    float* sEj1 = sm + OFF_J1;
    float* sEj2 = sm + OFF_J2;

    int t    = threadIdx.x;
    int lane = t & 31;
    int warp = t >> 5;
    int i0   = blockIdx.x * BM;
    int js   = blockIdx.y;
    int j0b  = js * (Nn / JSPLIT);
    int h    = warp & 3;                 // head
    int q    = warp >> 2;                // m-quarter (32 rows)

    sE1[t] = g_Ei1[i0 * HH + t];
    sE2[t] = g_Ei2[i0 * HH + t];
#pragma unroll
    for (int p = 0; p < 8; p++) {        // whole js-slice Ej tables -> smem
        int idx = p * 512 + t;
        sEj1[idx] = g_Ej1[j0b * HH + idx];
        sEj2[idx] = g_Ej2[j0b * HH + idx];
    }
    __syncthreads();

    float acc[2][8][4];
#pragma unroll
    for (int it = 0; it < 2; it++)
#pragma unroll
        for (int n = 0; n < 8; n++)
#pragma unroll
            for (int c = 0; c < 4; c++) acc[it][n][c] = 0.f;
    float dA[2][2] = {{0.f, 0.f}, {0.f, 0.f}};

    int boff = (lane >> 2) * 8 + (lane & 3) * 2;
    const long arow = (long)(i0 + warp * 8) * Nn + lane;   // this thread's adj base

    float av[8];

    // ---- prologue: load + build chunk 0 into buf 0 ----
#pragma unroll
    for (int r = 0; r < 8; r++) av[r] = __ldg(&adj[arow + (long)r * Nn + j0b]);
    {
        float4 Ej1 = *(const float4*)&sEj1[lane * 4];
        float4 Ej2 = *(const float4*)&sEj2[lane * 4];
        unsigned* W0 = (unsigned*)sm;
#pragma unroll
        for (int r = 0; r < 8; r++) {
            int i = warp * 8 + r;
            float em = (av[r] == 0.f) ? 0.f : __expf(av[r]);
            float4 e1 = *(const float4*)&sE1[i * 4];
            float4 e2 = *(const float4*)&sE2[i * 4];
            W0[0 * BM * SWP + i * SWP + lane] = tf32r(em * fmaxf(e1.x * Ej1.x, e2.x * Ej2.x));
            W0[1 * BM * SWP + i * SWP + lane] = tf32r(em * fmaxf(e1.y * Ej1.y, e2.y * Ej2.y));
            W0[2 * BM * SWP + i * SWP + lane] = tf32r(em * fmaxf(e1.z * Ej1.z, e2.z * Ej2.z));
            W0[3 * BM * SWP + i * SWP + lane] = tf32r(em * fmaxf(e1.w * Ej1.w, e2.w * Ej2.w));
        }
    }
    __syncthreads();

    for (int cc = 0; cc < NCH; cc++) {
        int buf = cc & 1;

        // ---- (a) issue adj loads for chunk cc+1 (latency hides under MMAs) ----
        if (cc + 1 < NCH) {
            int j0 = j0b + (cc + 1) * BK;
#pragma unroll
            for (int r = 0; r < 8; r++) av[r] = __ldg(&adj[arow + (long)r * Nn + j0]);
        }

        // ---- (b) mma chunk cc from buf; B direct from L2-resident g_Yp ----
        {
            int gb = (j0b + cc * BK) >> 3;
            const unsigned* Wp = (const unsigned*)(sm + buf * SWBUF)
                                 + h * BM * SWP + (q * 32) * SWP;
            int r = lane >> 2;
#pragma unroll
            for (int k = 0; k < 4; k++) {
                int col = k * 8 + (lane & 3);
                unsigned a0[4], a1[4];
                a0[0] = Wp[(r +  0) * SWP + col];     a0[1] = Wp[(r +  8) * SWP + col];
                a0[2] = Wp[(r +  0) * SWP + col + 4]; a0[3] = Wp[(r +  8) * SWP + col + 4];
                a1[0] = Wp[(r + 16) * SWP + col];     a1[1] = Wp[(r + 24) * SWP + col];
                a1[2] = Wp[(r + 16) * SWP + col + 4]; a1[3] = Wp[(r + 24) * SWP + col + 4];
                // denominator partials on fma pipe (tf32 bits are valid fp32)
                dA[0][0] += __uint_as_float(a0[0]) + __uint_as_float(a0[2]);
                dA[0][1] += __uint_as_float(a0[1]) + __uint_as_float(a0[3]);
                dA[1][0] += __uint_as_float(a1[0]) + __uint_as_float(a1[2]);
                dA[1][1] += __uint_as_float(a1[1]) + __uint_as_float(a1[3]);
                const float* Bb = g_Yp + (size_t)(h * 512 + gb + k) * 512;
#pragma unroll
                for (int n = 0; n < 8; n++) {
                    float2 bv = *(const float2*)&Bb[n * 64 + boff];
                    unsigned b0 = __float_as_uint(bv.x), b1 = __float_as_uint(bv.y);
                    mma8(acc[0][n], a0, b0, b1);
                    mma8(acc[1][n], a1, b0, b1);
                }
            }
        }

        // ---- (c) build chunk cc+1 into other buffer (adj data has arrived) ----
        if (cc + 1 < NCH) {
            int jr0 = (cc + 1) * BK + lane;
            float4 Ej1 = *(const float4*)&sEj1[jr0 * 4];
            float4 Ej2 = *(const float4*)&sEj2[jr0 * 4];
            unsigned* W0 = (unsigned*)(sm + (buf ^ 1) * SWBUF);
#pragma unroll
            for (int r = 0; r < 8; r++) {
                int i = warp * 8 + r;
                float em = (av[r] == 0.f) ? 0.f : __expf(av[r]);
                float4 e1 = *(const float4*)&sE1[i * 4];
                float4 e2 = *(const float4*)&sE2[i * 4];
                W0[0 * BM * SWP + i * SWP + lane] = tf32r(em * fmaxf(e1.x * Ej1.x, e2.x * Ej2.x));
                W0[1 * BM * SWP + i * SWP + lane] = tf32r(em * fmaxf(e1.y * Ej1.y, e2.y * Ej2.y));
                W0[2 * BM * SWP + i * SWP + lane] = tf32r(em * fmaxf(e1.z * Ej1.z, e2.z * Ej2.z));
                W0[3 * BM * SWP + i * SWP + lane] = tf32r(em * fmaxf(e1.w * Ej1.w, e2.w * Ej2.w));
            }
        }
        __syncthreads();
    }

    // ---- epilogue ----
    int rb = i0 + q * 32;
    int r  = lane >> 2;
    float* P = g_part[js];
#pragma unroll
    for (int it = 0; it < 2; it++) {
        int r0 = rb + it * 16 + r;
#pragma unroll
        for (int n = 0; n < 8; n++) {
            int cb = h * 64 + n * 8 + (lane & 3) * 2;
            *(float2*)&P[(size_t)r0 * HD + cb]       = make_float2(acc[it][n][0], acc[it][n][1]);
            *(float2*)&P[(size_t)(r0 + 8) * HD + cb] = make_float2(acc[it][n][2], acc[it][n][3]);
        }
        float d0 = dA[it][0], d1 = dA[it][1];
        d0 += __shfl_xor_sync(0xffffffffu, d0, 1);
        d0 += __shfl_xor_sync(0xffffffffu, d0, 2);
        d1 += __shfl_xor_sync(0xffffffffu, d1, 1);
        d1 += __shfl_xor_sync(0xffffffffu, d1, 2);
        if ((lane & 3) == 0) {
            g_denp[js][r0 * HH + h]       = d0;
            g_denp[js][(r0 + 8) * HH + h] = d1;
        }
    }
}

// ---------------- K4: combine splits, normalize, ELU -------------------------
__global__ __launch_bounds__(256) void k4_out(float* __restrict__ out) {
    int idx = blockIdx.x * 256 + threadIdx.x;
    int i   = idx >> 8;
    int hh  = (idx >> 6) & 3;
    float num = 0.f, den = 0.f;
#pragma unroll
    for (int s = 0; s < JSPLIT; s++) {
        num += g_part[s][idx];
        den += g_denp[s][i * HH + hh];
    }
    float v = (den != 0.f) ? (num / den) : g_Wh[idx];   // all-masked -> self loop
    out[idx] = (v > 0.f) ? v : expm1f(v);
}

// ---------------- launch ------------------------------------------------------
extern "C" void kernel_launch(void* const* d_in, const int* in_sizes, int n_in,
                              void* d_out, int out_size) {
    const float* h   = (const float*)d_in[0];
    const float* adj = (const float*)d_in[1];
    const float* W   = (const float*)d_in[2];
    const float* a   = (const float*)d_in[3];
    float* out = (float*)d_out;

    k0_nop<<<1, 32>>>();
    k1_gemm<<<dim3(HD / 64, Nn / 64), 256>>>(h, W);
    k2_e<<<Nn, 256>>>(a);

    cudaFuncSetAttribute((const void*)k3_main,
                         cudaFuncAttributeMaxDynamicSharedMemorySize, SMEM_K3);
    k3_main<<<dim3(Nn / BM, JSPLIT), 512, SMEM_K3>>>(adj);

    k4_out<<<Nn, 256>>>(out);
}

// round 9
// speedup vs baseline: 1.4037x; 1.4037x over previous
#include <cuda_runtime.h>
#include <cstdint>

#define Nn     4096
#define IND    256
#define HH     4
#define DD     64
#define HD     256
#define JSPLIT 4
#define BM     128
#define BK     32
#define NCH    ((Nn / JSPLIT) / BK)     // 32 chunks
#define SWP    36                        // sW row stride (floats) -> conflict-free frags

// ---------------- scratch (device globals; no allocation allowed) ------------
__device__ __align__(16) float g_Wh [Nn * HD];            // fp32 Wh [node][h*64+d]
__device__ __align__(16) float g_Yp [HH * 512 * DD * 8];  // tf32 [h][g][d][jj'] frag order
__device__ __align__(16) float g_Ei1[Nn * HH];            // exp(e_i)
__device__ __align__(16) float g_Ei2[Nn * HH];            // exp(0.2 e_i)
__device__ __align__(16) float g_Ej1[Nn * HH];            // exp(e_j)
__device__ __align__(16) float g_Ej2[Nn * HH];            // exp(0.2 e_j)
__device__ __align__(16) float g_part[JSPLIT][Nn * HD];
__device__ __align__(16) float g_denp[JSPLIT][Nn * HH];
__device__ int g_nop;

__device__ __forceinline__ unsigned tf32r(float x) {
    unsigned u;
    asm("cvt.rna.tf32.f32 %0, %1;" : "=r"(u) : "f"(x));
    return u;
}
__device__ __forceinline__ void mma8(float* c, const unsigned* a, unsigned b0, unsigned b1) {
    asm volatile(
        "mma.sync.aligned.m16n8k8.row.col.f32.tf32.tf32.f32 "
        "{%0,%1,%2,%3}, {%4,%5,%6,%7}, {%8,%9}, {%0,%1,%2,%3};"
        : "+f"(c[0]), "+f"(c[1]), "+f"(c[2]), "+f"(c[3])
        : "r"(a[0]), "r"(a[1]), "r"(a[2]), "r"(a[3]), "r"(b0), "r"(b1));
}
__device__ __forceinline__ void cpa16(uint32_t dst, const void* src) {
    asm volatile("cp.async.ca.shared.global [%0], [%1], 16;"
                 :: "r"(dst), "l"(src) : "memory");
}

// dummy launch: keeps ncu's fixed capture slot on k3
__global__ void k0_nop() { g_nop = 0; }

// ---------------- K1: Wh = h @ W ; also emit fragment-ordered tf32 copy ------
__global__ __launch_bounds__(256) void k1_gemm(const float* __restrict__ h,
                                               const float* __restrict__ W) {
    __shared__ float As[16][64 + 4];
    __shared__ float Bs[16][64];
    __shared__ float til[64][68];
    int t  = threadIdx.x;
    int tx = t & 15, ty = t >> 4;
    int j0 = blockIdx.y * 64;
    int n0 = blockIdx.x * 64;
    float acc[4][4];
#pragma unroll
    for (int m = 0; m < 4; m++)
#pragma unroll
        for (int c = 0; c < 4; c++) acc[m][c] = 0.f;

    for (int k0 = 0; k0 < IND; k0 += 16) {
        int arow = t >> 2, akq = (t & 3) * 4;
        float4 av = *(const float4*)&h[(j0 + arow) * IND + k0 + akq];
        As[akq + 0][arow] = av.x; As[akq + 1][arow] = av.y;
        As[akq + 2][arow] = av.z; As[akq + 3][arow] = av.w;
        int brow = t >> 4, bcol = (t & 15) * 4;
        *(float4*)&Bs[brow][bcol] = *(const float4*)&W[(k0 + brow) * HD + n0 + bcol];
        __syncthreads();
#pragma unroll
        for (int kk = 0; kk < 16; kk++) {
            float a0 = As[kk][ty * 4 + 0], a1 = As[kk][ty * 4 + 1];
            float a2 = As[kk][ty * 4 + 2], a3 = As[kk][ty * 4 + 3];
            float4 b = *(float4*)&Bs[kk][tx * 4];
            acc[0][0] += a0 * b.x; acc[0][1] += a0 * b.y; acc[0][2] += a0 * b.z; acc[0][3] += a0 * b.w;
            acc[1][0] += a1 * b.x; acc[1][1] += a1 * b.y; acc[1][2] += a1 * b.z; acc[1][3] += a1 * b.w;
            acc[2][0] += a2 * b.x; acc[2][1] += a2 * b.y; acc[2][2] += a2 * b.z; acc[2][3] += a2 * b.w;
            acc[3][0] += a3 * b.x; acc[3][1] += a3 * b.y; acc[3][2] += a3 * b.z; acc[3][3] += a3 * b.w;
        }
        __syncthreads();
    }
#pragma unroll
    for (int m = 0; m < 4; m++) {
        *(float4*)&til[ty * 4 + m][tx * 4] =
            make_float4(acc[m][0], acc[m][1], acc[m][2], acc[m][3]);
#pragma unroll
        for (int c = 0; c < 4; c++)
            g_Wh[(j0 + ty * 4 + m) * HD + n0 + tx * 4 + c] = acc[m][c];
    }
    __syncthreads();

    int hh = blockIdx.x;
    float* dst = g_Yp + (hh * 512 + blockIdx.y * 8) * 512;
#pragma unroll
    for (int it = 0; it < 16; it++) {
        int idx = it * 256 + t;
        int jj  = ((idx & 1) << 2) | ((idx >> 1) & 3);   // inverse perm
        float v = til[(idx >> 9) * 8 + jj][(idx >> 3) & 63];
        dst[idx] = __uint_as_float(tf32r(v));
    }
}

// ---------------- K2: per-node attention logits + exps -----------------------
__global__ __launch_bounds__(256) void k2_e(const float* __restrict__ a) {
    int i = blockIdx.x;
    int t = threadIdx.x;
    int hh = t >> 6, d = t & 63;
    float v  = g_Wh[i * HD + t];
    float ei = v * a[hh * (2 * DD) + d];
    float ej = v * a[hh * (2 * DD) + DD + d];
#pragma unroll
    for (int o = 16; o > 0; o >>= 1) {
        ei += __shfl_down_sync(0xffffffffu, ei, o);
        ej += __shfl_down_sync(0xffffffffu, ej, o);
    }
    __shared__ float sei[8], sej[8];
    int w = t >> 5;
    if ((t & 31) == 0) { sei[w] = ei; sej[w] = ej; }
    __syncthreads();
    if (t < HH) {
        float EI = sei[2 * t] + sei[2 * t + 1];
        float EJ = sej[2 * t] + sej[2 * t + 1];
        g_Ei1[i * HH + t] = __expf(EI);
        g_Ei2[i * HH + t] = __expf(0.2f * EI);
        g_Ej1[i * HH + t] = __expf(EJ);
        g_Ej2[i * HH + t] = __expf(0.2f * EJ);
    }
}

// ---------------- K3: fused weight build + mma.sync tf32 contraction ---------
// 16 warps = 4 heads x 4 m-quarters; BM=128 rows; 128 CTAs (1 wave).
// Pipeline per chunk: cp.async adj(cc+1)->smem; MMA(cc); wait+build(cc+1); bar.
// smem: sW 2 x [4h][128][SWP], sE1/sE2[512], sEj1/sEj2[4096], sAdj 2 x [128][32]
#define SWBUF   (HH * BM * SWP)          // 18432 floats
#define OFF_E1  (2 * SWBUF)
#define OFF_E2  (OFF_E1 + 512)
#define OFF_J1  (OFF_E2 + 512)
#define OFF_J2  (OFF_J1 + 4096)
#define OFF_ADJ (OFF_J2 + 4096)          // 2 x 4096 floats
#define SMEM_K3 ((OFF_ADJ + 2 * 4096) * 4)   // 217088 B

__global__ __launch_bounds__(512, 1) void k3_main(const float* __restrict__ adj) {
    extern __shared__ float sm[];
    float* sE1  = sm + OFF_E1;
    float* sE2  = sm + OFF_E2;
    float* sEj1 = sm + OFF_J1;
    float* sEj2 = sm + OFF_J2;
    float* sAdj = sm + OFF_ADJ;

    uint32_t sadj_u32;
    asm("{ .reg .u64 t; cvta.to.shared.u64 t, %1; cvt.u32.u64 %0, t; }"
        : "=r"(sadj_u32) : "l"(sAdj));

    int t    = threadIdx.x;
    int lane = t & 31;
    int warp = t >> 5;
    int i0   = blockIdx.x * BM;
    int js   = blockIdx.y;
    int j0b  = js * (Nn / JSPLIT);
    int h    = warp & 3;                 // head
    int q    = warp >> 2;                // m-quarter (32 rows)

    sE1[t] = g_Ei1[i0 * HH + t];
    sE2[t] = g_Ei2[i0 * HH + t];
#pragma unroll
    for (int p = 0; p < 8; p++) {        // whole js-slice Ej tables -> smem
        int idx = p * 512 + t;
        sEj1[idx] = g_Ej1[j0b * HH + idx];
        sEj2[idx] = g_Ej2[j0b * HH + idx];
    }

    float acc[2][8][4];
#pragma unroll
    for (int it = 0; it < 2; it++)
#pragma unroll
        for (int n = 0; n < 8; n++)
#pragma unroll
            for (int c = 0; c < 4; c++) acc[it][n][c] = 0.f;
    float dA[2][2] = {{0.f, 0.f}, {0.f, 0.f}};

    int boff = (lane >> 2) * 8 + (lane & 3) * 2;

    // stage coords for this thread's 2 cp.async per chunk
    int srow0 = warp * 8 + (lane >> 3);             // rows +0 and +4
    int scj   = (lane & 7) * 4;

    // ---- prologue: stage + build chunk 0 into buf 0 ----
#pragma unroll
    for (int rr = 0; rr < 2; rr++) {
        int row = srow0 + rr * 4;
        cpa16(sadj_u32 + (size_t)(row * 32 + scj) * 4,
              &adj[(long)(i0 + row) * Nn + j0b + scj]);
    }
    asm volatile("cp.async.commit_group;" ::: "memory");
    asm volatile("cp.async.wait_group 0;" ::: "memory");
    __syncwarp();
    {
        float4 Ej1 = *(const float4*)&sEj1[lane * 4];
        float4 Ej2 = *(const float4*)&sEj2[lane * 4];
        unsigned* W0 = (unsigned*)sm;
#pragma unroll
        for (int r = 0; r < 8; r++) {
            int i = warp * 8 + r;
            float avr = sAdj[i * 32 + lane];
            float em = (avr == 0.f) ? 0.f : __expf(avr);
            float4 e1 = *(const float4*)&sE1[i * 4];
            float4 e2 = *(const float4*)&sE2[i * 4];
            W0[0 * BM * SWP + i * SWP + lane] = tf32r(em * fmaxf(e1.x * Ej1.x, e2.x * Ej2.x));
            W0[1 * BM * SWP + i * SWP + lane] = tf32r(em * fmaxf(e1.y * Ej1.y, e2.y * Ej2.y));
            W0[2 * BM * SWP + i * SWP + lane] = tf32r(em * fmaxf(e1.z * Ej1.z, e2.z * Ej2.z));
            W0[3 * BM * SWP + i * SWP + lane] = tf32r(em * fmaxf(e1.w * Ej1.w, e2.w * Ej2.w));
        }
    }
    __syncthreads();

    for (int cc = 0; cc < NCH; cc++) {
        int buf = cc & 1;

        // ---- (a) cp.async adj tile for chunk cc+1 (engine-side, no regs) ----
        if (cc + 1 < NCH) {
            int j0 = j0b + (cc + 1) * BK;
            uint32_t dst = sadj_u32 + (uint32_t)((buf ^ 1) * 4096) * 4;
#pragma unroll
            for (int rr = 0; rr < 2; rr++) {
                int row = srow0 + rr * 4;
                cpa16(dst + (uint32_t)(row * 32 + scj) * 4,
                      &adj[(long)(i0 + row) * Nn + j0 + scj]);
            }
        }
        asm volatile("cp.async.commit_group;" ::: "memory");

        // ---- (b) mma chunk cc from buf; B direct from L2-resident g_Yp ----
        {
            int gb = (j0b + cc * BK) >> 3;
            const unsigned* Wp = (const unsigned*)(sm + buf * SWBUF)
                                 + h * BM * SWP + (q * 32) * SWP;
            int r = lane >> 2;
#pragma unroll
            for (int k = 0; k < 4; k++) {
                int col = k * 8 + (lane & 3);
                unsigned a0[4], a1[4];
                a0[0] = Wp[(r +  0) * SWP + col];     a0[1] = Wp[(r +  8) * SWP + col];
                a0[2] = Wp[(r +  0) * SWP + col + 4]; a0[3] = Wp[(r +  8) * SWP + col + 4];
                a1[0] = Wp[(r + 16) * SWP + col];     a1[1] = Wp[(r + 24) * SWP + col];
                a1[2] = Wp[(r + 16) * SWP + col + 4]; a1[3] = Wp[(r + 24) * SWP + col + 4];
                // denominator partials on fma pipe (tf32 bits are valid fp32)
                dA[0][0] += __uint_as_float(a0[0]) + __uint_as_float(a0[2]);
                dA[0][1] += __uint_as_float(a0[1]) + __uint_as_float(a0[3]);
                dA[1][0] += __uint_as_float(a1[0]) + __uint_as_float(a1[2]);
                dA[1][1] += __uint_as_float(a1[1]) + __uint_as_float(a1[3]);
                const float* Bb = g_Yp + (size_t)(h * 512 + gb + k) * 512;
#pragma unroll
                for (int n = 0; n < 8; n++) {
                    float2 bv = *(const float2*)&Bb[n * 64 + boff];
                    unsigned b0 = __float_as_uint(bv.x), b1 = __float_as_uint(bv.y);
                    mma8(acc[0][n], a0, b0, b1);
                    mma8(acc[1][n], a1, b0, b1);
                }
            }
        }

        // ---- (c) build chunk cc+1 (adj tile has landed via cp.async) ----
        if (cc + 1 < NCH) {
            asm volatile("cp.async.wait_group 0;" ::: "memory");
            __syncwarp();
            const float* Ad = sAdj + (buf ^ 1) * 4096;
            int jr0 = (cc + 1) * BK + lane;
            float4 Ej1 = *(const float4*)&sEj1[jr0 * 4];
            float4 Ej2 = *(const float4*)&sEj2[jr0 * 4];
            unsigned* W0 = (unsigned*)(sm + (buf ^ 1) * SWBUF);
#pragma unroll
            for (int r = 0; r < 8; r++) {
                int i = warp * 8 + r;
                float avr = Ad[i * 32 + lane];
                float em = (avr == 0.f) ? 0.f : __expf(avr);
                float4 e1 = *(const float4*)&sE1[i * 4];
                float4 e2 = *(const float4*)&sE2[i * 4];
                W0[0 * BM * SWP + i * SWP + lane] = tf32r(em * fmaxf(e1.x * Ej1.x, e2.x * Ej2.x));
                W0[1 * BM * SWP + i * SWP + lane] = tf32r(em * fmaxf(e1.y * Ej1.y, e2.y * Ej2.y));
                W0[2 * BM * SWP + i * SWP + lane] = tf32r(em * fmaxf(e1.z * Ej1.z, e2.z * Ej2.z));
                W0[3 * BM * SWP + i * SWP + lane] = tf32r(em * fmaxf(e1.w * Ej1.w, e2.w * Ej2.w));
            }
        }
        __syncthreads();
    }

    // ---- epilogue ----
    int rb = i0 + q * 32;
    int r  = lane >> 2;
    float* P = g_part[js];
#pragma unroll
    for (int it = 0; it < 2; it++) {
        int r0 = rb + it * 16 + r;
#pragma unroll
        for (int n = 0; n < 8; n++) {
            int cb = h * 64 + n * 8 + (lane & 3) * 2;
            *(float2*)&P[(size_t)r0 * HD + cb]       = make_float2(acc[it][n][0], acc[it][n][1]);
            *(float2*)&P[(size_t)(r0 + 8) * HD + cb] = make_float2(acc[it][n][2], acc[it][n][3]);
        }
        float d0 = dA[it][0], d1 = dA[it][1];
        d0 += __shfl_xor_sync(0xffffffffu, d0, 1);
        d0 += __shfl_xor_sync(0xffffffffu, d0, 2);
        d1 += __shfl_xor_sync(0xffffffffu, d1, 1);
        d1 += __shfl_xor_sync(0xffffffffu, d1, 2);
        if ((lane & 3) == 0) {
            g_denp[js][r0 * HH + h]       = d0;
            g_denp[js][(r0 + 8) * HH + h] = d1;
        }
    }
}

// ---------------- K4: combine splits, normalize, ELU -------------------------
__global__ __launch_bounds__(256) void k4_out(float* __restrict__ out) {
    int idx = blockIdx.x * 256 + threadIdx.x;
    int i   = idx >> 8;
    int hh  = (idx >> 6) & 3;
    float num = 0.f, den = 0.f;
#pragma unroll
    for (int s = 0; s < JSPLIT; s++) {
        num += g_part[s][idx];
        den += g_denp[s][i * HH + hh];
    }
    float v = (den != 0.f) ? (num / den) : g_Wh[idx];   // all-masked -> self loop
    out[idx] = (v > 0.f) ? v : expm1f(v);
}

// ---------------- launch ------------------------------------------------------
extern "C" void kernel_launch(void* const* d_in, const int* in_sizes, int n_in,
                              void* d_out, int out_size) {
    const float* h   = (const float*)d_in[0];
    const float* adj = (const float*)d_in[1];
    const float* W   = (const float*)d_in[2];
    const float* a   = (const float*)d_in[3];
    float* out = (float*)d_out;

    k0_nop<<<1, 32>>>();
    k1_gemm<<<dim3(HD / 64, Nn / 64), 256>>>(h, W);
    k2_e<<<Nn, 256>>>(a);

    cudaFuncSetAttribute((const void*)k3_main,
                         cudaFuncAttributeMaxDynamicSharedMemorySize, SMEM_K3);
    k3_main<<<dim3(Nn / BM, JSPLIT), 512, SMEM_K3>>>(adj);

    k4_out<<<Nn, 256>>>(out);
}

// round 10
// speedup vs baseline: 1.5831x; 1.1279x over previous
#include <cuda_runtime.h>
#include <cstdint>

#define Nn     4096
#define IND    256
#define HH     4
#define DD     64
#define HD     256
#define JSPLIT 4
#define BM     128
#define BK     32
#define NCH    ((Nn / JSPLIT) / BK)     // 32 chunks
#define SWP    36                        // sW row stride (floats) -> conflict-free frags

// ---------------- scratch (device globals; no allocation allowed) ------------
__device__ __align__(16) float g_Wh [Nn * HD];            // fp32 Wh [node][h*64+d]
__device__ __align__(16) float g_Yp [HH * 512 * DD * 8];  // tf32 [h][g][d][jj'] frag order
__device__ __align__(16) float g_Ei1[Nn * HH];            // exp(e_i)
__device__ __align__(16) float g_Ei2[Nn * HH];            // exp(0.2 e_i)
__device__ __align__(16) float g_Ej1[Nn * HH];            // exp(e_j)
__device__ __align__(16) float g_Ej2[Nn * HH];            // exp(0.2 e_j)
__device__ __align__(16) float g_part[JSPLIT][Nn * HD];
__device__ __align__(16) float g_denp[JSPLIT][Nn * HH];
__device__ int g_nop;

__device__ __forceinline__ unsigned tf32r(float x) {
    unsigned u;
    asm("cvt.rna.tf32.f32 %0, %1;" : "=r"(u) : "f"(x));
    return u;
}
__device__ __forceinline__ void mma8(float* c, const unsigned* a, unsigned b0, unsigned b1) {
    asm volatile(
        "mma.sync.aligned.m16n8k8.row.col.f32.tf32.tf32.f32 "
        "{%0,%1,%2,%3}, {%4,%5,%6,%7}, {%8,%9}, {%0,%1,%2,%3};"
        : "+f"(c[0]), "+f"(c[1]), "+f"(c[2]), "+f"(c[3])
        : "r"(a[0]), "r"(a[1]), "r"(a[2]), "r"(a[3]), "r"(b0), "r"(b1));
}

// dummy launch: keeps ncu's fixed capture slot on k3
__global__ void k0_nop() { g_nop = 0; }

// ---------------- K1: Wh = h @ W ; also emit fragment-ordered tf32 copy ------
__global__ __launch_bounds__(256) void k1_gemm(const float* __restrict__ h,
                                               const float* __restrict__ W) {
    __shared__ float As[16][64 + 4];
    __shared__ float Bs[16][64];
    __shared__ float til[64][68];
    int t  = threadIdx.x;
    int tx = t & 15, ty = t >> 4;
    int j0 = blockIdx.y * 64;
    int n0 = blockIdx.x * 64;
    float acc[4][4];
#pragma unroll
    for (int m = 0; m < 4; m++)
#pragma unroll
        for (int c = 0; c < 4; c++) acc[m][c] = 0.f;

    for (int k0 = 0; k0 < IND; k0 += 16) {
        int arow = t >> 2, akq = (t & 3) * 4;
        float4 av = *(const float4*)&h[(j0 + arow) * IND + k0 + akq];
        As[akq + 0][arow] = av.x; As[akq + 1][arow] = av.y;
        As[akq + 2][arow] = av.z; As[akq + 3][arow] = av.w;
        int brow = t >> 4, bcol = (t & 15) * 4;
        *(float4*)&Bs[brow][bcol] = *(const float4*)&W[(k0 + brow) * HD + n0 + bcol];
        __syncthreads();
#pragma unroll
        for (int kk = 0; kk < 16; kk++) {
            float a0 = As[kk][ty * 4 + 0], a1 = As[kk][ty * 4 + 1];
            float a2 = As[kk][ty * 4 + 2], a3 = As[kk][ty * 4 + 3];
            float4 b = *(float4*)&Bs[kk][tx * 4];
            acc[0][0] += a0 * b.x; acc[0][1] += a0 * b.y; acc[0][2] += a0 * b.z; acc[0][3] += a0 * b.w;
            acc[1][0] += a1 * b.x; acc[1][1] += a1 * b.y; acc[1][2] += a1 * b.z; acc[1][3] += a1 * b.w;
            acc[2][0] += a2 * b.x; acc[2][1] += a2 * b.y; acc[2][2] += a2 * b.z; acc[2][3] += a2 * b.w;
            acc[3][0] += a3 * b.x; acc[3][1] += a3 * b.y; acc[3][2] += a3 * b.z; acc[3][3] += a3 * b.w;
        }
        __syncthreads();
    }
#pragma unroll
    for (int m = 0; m < 4; m++) {
        *(float4*)&til[ty * 4 + m][tx * 4] =
            make_float4(acc[m][0], acc[m][1], acc[m][2], acc[m][3]);
#pragma unroll
        for (int c = 0; c < 4; c++)
            g_Wh[(j0 + ty * 4 + m) * HD + n0 + tx * 4 + c] = acc[m][c];
    }
    __syncthreads();

    int hh = blockIdx.x;
    float* dst = g_Yp + (hh * 512 + blockIdx.y * 8) * 512;
#pragma unroll
    for (int it = 0; it < 16; it++) {
        int idx = it * 256 + t;
        int jj  = ((idx & 1) << 2) | ((idx >> 1) & 3);   // inverse perm
        float v = til[(idx >> 9) * 8 + jj][(idx >> 3) & 63];
        dst[idx] = __uint_as_float(tf32r(v));
    }
}

// ---------------- K2: per-node attention logits + exps -----------------------
__global__ __launch_bounds__(256) void k2_e(const float* __restrict__ a) {
    int i = blockIdx.x;
    int t = threadIdx.x;
    int hh = t >> 6, d = t & 63;
    float v  = g_Wh[i * HD + t];
    float ei = v * a[hh * (2 * DD) + d];
    float ej = v * a[hh * (2 * DD) + DD + d];
#pragma unroll
    for (int o = 16; o > 0; o >>= 1) {
        ei += __shfl_down_sync(0xffffffffu, ei, o);
        ej += __shfl_down_sync(0xffffffffu, ej, o);
    }
    __shared__ float sei[8], sej[8];
    int w = t >> 5;
    if ((t & 31) == 0) { sei[w] = ei; sej[w] = ej; }
    __syncthreads();
    if (t < HH) {
        float EI = sei[2 * t] + sei[2 * t + 1];
        float EJ = sej[2 * t] + sej[2 * t + 1];
        g_Ei1[i * HH + t] = __expf(EI);
        g_Ei2[i * HH + t] = __expf(0.2f * EI);
        g_Ej1[i * HH + t] = __expf(EJ);
        g_Ej2[i * HH + t] = __expf(0.2f * EJ);
    }
}

// ---------------- K3: fused weight build + mma.sync tf32 contraction ---------
// ONE 1024-thread CTA per SM slot; 32 warps = 4 heads x 4 m-quarters x 2 n-halves.
// 64 regs/thread -> occ 50% (32/64 warps). BM=128; 128 CTAs (1 wave).
// smem: sW 2 x [4h][128][SWP], sE1/sE2[512], sEj1/sEj2[4096]
#define SWBUF  (HH * BM * SWP)           // 18432 floats
#define OFF_E1 (2 * SWBUF)
#define OFF_E2 (OFF_E1 + 512)
#define OFF_J1 (OFF_E2 + 512)
#define OFF_J2 (OFF_J1 + 4096)
#define SMEM_K3 ((OFF_J2 + 4096) * 4)    // 184320 B

__global__ __launch_bounds__(1024, 1) void k3_main(const float* __restrict__ adj) {
    extern __shared__ float sm[];
    float* sE1  = sm + OFF_E1;
    float* sE2  = sm + OFF_E2;
    float* sEj1 = sm + OFF_J1;
    float* sEj2 = sm + OFF_J2;

    int t    = threadIdx.x;
    int lane = t & 31;
    int warp = t >> 5;
    int i0   = blockIdx.x * BM;
    int js   = blockIdx.y;
    int j0b  = js * (Nn / JSPLIT);
    int h    = warp & 3;                 // head
    int q    = (warp >> 2) & 3;          // m-quarter (32 rows)
    int nh   = warp >> 4;                // n-half (32 of 64 cols)

    if (t < 512) { sE1[t] = g_Ei1[i0 * HH + t]; sE2[t] = g_Ei2[i0 * HH + t]; }
#pragma unroll
    for (int p = 0; p < 4; p++) {        // whole js-slice Ej tables -> smem
        int idx = p * 1024 + t;
        sEj1[idx] = g_Ej1[j0b * HH + idx];
        sEj2[idx] = g_Ej2[j0b * HH + idx];
    }
    __syncthreads();

    float acc[2][4][4];                  // m32 x n32 per warp
#pragma unroll
    for (int it = 0; it < 2; it++)
#pragma unroll
        for (int n = 0; n < 4; n++)
#pragma unroll
            for (int c = 0; c < 4; c++) acc[it][n][c] = 0.f;
    float dA[2][2] = {{0.f, 0.f}, {0.f, 0.f}};

    int boff = (lane >> 2) * 8 + (lane & 3) * 2;

    // ---- build chunk 0 (each warp: 4 rows, all 4 heads) ----
    {
        float4 Ej1 = *(const float4*)&sEj1[lane * 4];
        float4 Ej2 = *(const float4*)&sEj2[lane * 4];
        unsigned* W0 = (unsigned*)sm;
#pragma unroll
        for (int r = 0; r < 4; r++) {
            int i = warp * 4 + r;
            float av = __ldg(&adj[(long)(i0 + i) * Nn + j0b + lane]);
            float em = (av == 0.f) ? 0.f : __expf(av);
            float4 e1 = *(const float4*)&sE1[i * 4];
            float4 e2 = *(const float4*)&sE2[i * 4];
            W0[0 * BM * SWP + i * SWP + lane] = tf32r(em * fmaxf(e1.x * Ej1.x, e2.x * Ej2.x));
            W0[1 * BM * SWP + i * SWP + lane] = tf32r(em * fmaxf(e1.y * Ej1.y, e2.y * Ej2.y));
            W0[2 * BM * SWP + i * SWP + lane] = tf32r(em * fmaxf(e1.z * Ej1.z, e2.z * Ej2.z));
            W0[3 * BM * SWP + i * SWP + lane] = tf32r(em * fmaxf(e1.w * Ej1.w, e2.w * Ej2.w));
        }
    }
    __syncthreads();

    for (int cc = 0; cc < NCH; cc++) {
        int buf = cc & 1;

        // ---- build chunk cc+1 into other buffer (overlaps other warps' mma) ----
        if (cc + 1 < NCH) {
            int jr0 = (cc + 1) * BK + lane;
            float4 Ej1 = *(const float4*)&sEj1[jr0 * 4];
            float4 Ej2 = *(const float4*)&sEj2[jr0 * 4];
            unsigned* W0 = (unsigned*)(sm + (buf ^ 1) * SWBUF);
            int j0 = j0b + (cc + 1) * BK;
#pragma unroll
            for (int r = 0; r < 4; r++) {
                int i = warp * 4 + r;
                float av = __ldg(&adj[(long)(i0 + i) * Nn + j0 + lane]);
                float em = (av == 0.f) ? 0.f : __expf(av);
                float4 e1 = *(const float4*)&sE1[i * 4];
                float4 e2 = *(const float4*)&sE2[i * 4];
                W0[0 * BM * SWP + i * SWP + lane] = tf32r(em * fmaxf(e1.x * Ej1.x, e2.x * Ej2.x));
                W0[1 * BM * SWP + i * SWP + lane] = tf32r(em * fmaxf(e1.y * Ej1.y, e2.y * Ej2.y));
                W0[2 * BM * SWP + i * SWP + lane] = tf32r(em * fmaxf(e1.z * Ej1.z, e2.z * Ej2.z));
                W0[3 * BM * SWP + i * SWP + lane] = tf32r(em * fmaxf(e1.w * Ej1.w, e2.w * Ej2.w));
            }
        }

        // ---- mma chunk cc from buf; B direct from L2-resident g_Yp ----
        {
            int gb = (j0b + cc * BK) >> 3;
            const unsigned* Wp = (const unsigned*)(sm + buf * SWBUF)
                                 + h * BM * SWP + (q * 32) * SWP;
            int r = lane >> 2;
#pragma unroll
            for (int k = 0; k < 4; k++) {
                int col = k * 8 + (lane & 3);
                unsigned a0[4], a1[4];
                a0[0] = Wp[(r +  0) * SWP + col];     a0[1] = Wp[(r +  8) * SWP + col];
                a0[2] = Wp[(r +  0) * SWP + col + 4]; a0[3] = Wp[(r +  8) * SWP + col + 4];
                a1[0] = Wp[(r + 16) * SWP + col];     a1[1] = Wp[(r + 24) * SWP + col];
                a1[2] = Wp[(r + 16) * SWP + col + 4]; a1[3] = Wp[(r + 24) * SWP + col + 4];
                if (nh == 0) {           // denominator partials on fma pipe
                    dA[0][0] += __uint_as_float(a0[0]) + __uint_as_float(a0[2]);
                    dA[0][1] += __uint_as_float(a0[1]) + __uint_as_float(a0[3]);
                    dA[1][0] += __uint_as_float(a1[0]) + __uint_as_float(a1[2]);
                    dA[1][1] += __uint_as_float(a1[1]) + __uint_as_float(a1[3]);
                }
                const float* Bb = g_Yp + (size_t)(h * 512 + gb + k) * 512 + nh * 4 * 64;
#pragma unroll
                for (int n = 0; n < 4; n++) {
                    float2 bv = *(const float2*)&Bb[n * 64 + boff];
                    unsigned b0 = __float_as_uint(bv.x), b1 = __float_as_uint(bv.y);
                    mma8(acc[0][n], a0, b0, b1);
                    mma8(acc[1][n], a1, b0, b1);
                }
            }
        }
        __syncthreads();
    }

    // ---- epilogue ----
    int rb = i0 + q * 32;
    int r  = lane >> 2;
    float* P = g_part[js];
#pragma unroll
    for (int it = 0; it < 2; it++) {
        int r0 = rb + it * 16 + r;
#pragma unroll
        for (int n = 0; n < 4; n++) {
            int cb = h * 64 + nh * 32 + n * 8 + (lane & 3) * 2;
            *(float2*)&P[(size_t)r0 * HD + cb]       = make_float2(acc[it][n][0], acc[it][n][1]);
            *(float2*)&P[(size_t)(r0 + 8) * HD + cb] = make_float2(acc[it][n][2], acc[it][n][3]);
        }
        if (nh == 0) {
            float d0 = dA[it][0], d1 = dA[it][1];
            d0 += __shfl_xor_sync(0xffffffffu, d0, 1);
            d0 += __shfl_xor_sync(0xffffffffu, d0, 2);
            d1 += __shfl_xor_sync(0xffffffffu, d1, 1);
            d1 += __shfl_xor_sync(0xffffffffu, d1, 2);
            if ((lane & 3) == 0) {
                g_denp[js][r0 * HH + h]       = d0;
                g_denp[js][(r0 + 8) * HH + h] = d1;
            }
        }
    }
}

// ---------------- K4: combine splits, normalize, ELU -------------------------
__global__ __launch_bounds__(256) void k4_out(float* __restrict__ out) {
    int idx = blockIdx.x * 256 + threadIdx.x;
    int i   = idx >> 8;
    int hh  = (idx >> 6) & 3;
    float num = 0.f, den = 0.f;
#pragma unroll
    for (int s = 0; s < JSPLIT; s++) {
        num += g_part[s][idx];
        den += g_denp[s][i * HH + hh];
    }
    float v = (den != 0.f) ? (num / den) : g_Wh[idx];   // all-masked -> self loop
    out[idx] = (v > 0.f) ? v : expm1f(v);
}

// ---------------- launch ------------------------------------------------------
extern "C" void kernel_launch(void* const* d_in, const int* in_sizes, int n_in,
                              void* d_out, int out_size) {
    const float* h   = (const float*)d_in[0];
    const float* adj = (const float*)d_in[1];
    const float* W   = (const float*)d_in[2];
    const float* a   = (const float*)d_in[3];
    float* out = (float*)d_out;

    k0_nop<<<1, 32>>>();
    k1_gemm<<<dim3(HD / 64, Nn / 64), 256>>>(h, W);
    k2_e<<<Nn, 256>>>(a);

    cudaFuncSetAttribute((const void*)k3_main,
                         cudaFuncAttributeMaxDynamicSharedMemorySize, SMEM_K3);
    k3_main<<<dim3(Nn / BM, JSPLIT), 1024, SMEM_K3>>>(adj);

    k4_out<<<Nn, 256>>>(out);
}